// round 14
// baseline (speedup 1.0000x reference)
#include <cuda_runtime.h>
#include <cstdint>

// ---------------- problem constants ----------------
#define NB 64
#define NS 1024
#define NH 512
#define NM (NB*NS)
#define NN 512
#define WSTRIDE (512*512)
#define PLANE ((size_t)NM*NN)

// GEMM tiling: CTA 64x128, 8 warps (2x4), warp tile 32x32, K-chunk 64 (int8).
// Persistent: 296 CTAs (2/SM), pipeline continuous across tiles.
#define BM 64
#define BN 128
#define KCH 64
#define ROWB 64
#define A_TILE_B (64*ROWB)      // 4096
#define B_TILE_B (128*ROWB)     // 8192
#define SLOT (2*A_TILE_B + 2*B_TILE_B)  // 24576
#define NSLOT 4
#define SMEM_BYTES (NSLOT*SLOT) // 98304 -> 2 CTAs/SM
#define NPERS 296               // persistent CTAs (2 x 148 SMs)
#define NTILES 4096             // (512/BN=4) x (65536/BM=1024)

#define A_HI_OFF 0
#define A_LO_OFF A_TILE_B
#define B_HI_OFF (2*A_TILE_B)
#define B_LO_OFF (2*A_TILE_B + B_TILE_B)

// ---------------- device scratch ----------------
__device__ int8_t g_qhi[(size_t)5*PLANE];   // act planes: 0=X 1=rh 2=h0 3=h1 4=h2
__device__ int8_t g_qlo[(size_t)5*PLANE];
__device__ int8_t g_wqh[(size_t)13*WSTRIDE];
__device__ int8_t g_wql[(size_t)13*WSTRIDE];
__device__ float  g_sbv[13*512];
__device__ float  g_z [PLANE];
__device__ float  g_ag[PLANE];
__device__ float  g_hz [NB*NH];
__device__ float  g_hr [NB*NH];
__device__ float  g_h0c[NB*NH];
__device__ float  g_part[2112];
__device__ float  g_sc[4];                   // sX, sH, invX, invH

// ---------------- helpers ----------------
__device__ __forceinline__ uint32_t smem_u32(const void* p) {
    uint32_t a;
    asm("{ .reg .u64 t; cvta.to.shared.u64 t, %1; cvt.u32.u64 %0, t; }" : "=r"(a) : "l"(p));
    return a;
}
__device__ __forceinline__ void cp_async16(uint32_t dst, const void* src) {
    asm volatile("cp.async.cg.shared.global [%0], [%1], 16;" :: "r"(dst), "l"(src) : "memory");
}
__device__ __forceinline__ void cp_commit() { asm volatile("cp.async.commit_group;" ::: "memory"); }
template<int N>
__device__ __forceinline__ void cp_wait() { asm volatile("cp.async.wait_group %0;" :: "n"(N) : "memory"); }
__device__ __forceinline__ void ldmatrix4(uint32_t& r0, uint32_t& r1, uint32_t& r2, uint32_t& r3, uint32_t addr) {
    asm volatile("ldmatrix.sync.aligned.m8n8.x4.shared.b16 {%0,%1,%2,%3}, [%4];"
                 : "=r"(r0), "=r"(r1), "=r"(r2), "=r"(r3) : "r"(addr));
}
__device__ __forceinline__ void mma_s8(int* d, const uint32_t* a, const uint32_t* b) {
    asm volatile("mma.sync.aligned.m16n8k32.row.col.s32.s8.s8.s32 "
        "{%0,%1,%2,%3}, {%4,%5,%6,%7}, {%8,%9}, {%0,%1,%2,%3};"
        : "+r"(d[0]), "+r"(d[1]), "+r"(d[2]), "+r"(d[3])
        : "r"(a[0]), "r"(a[1]), "r"(a[2]), "r"(a[3]), "r"(b[0]), "r"(b[1]));
}
__device__ __forceinline__ void quant16(float v, float invS, int8_t* hp, int8_t* lp) {
    int q = __float2int_rn(v * invS);
    q = max(-32512, min(32512, q));
    int h = (q + 128) >> 8;
    *hp = (int8_t)h;
    *lp = (int8_t)(q - (h << 8));
}

// ---------------- prep (3 launches) ----------------
__global__ void k_stat(const float4* __restrict__ x, const float* __restrict__ hs) {
    __shared__ float red[256];
    const int blk = blockIdx.x, t = threadIdx.x;
    float m = 0.f;
    if (blk < 2048) {
        const size_t n4 = PLANE / 4;
        for (size_t i = (size_t)blk * 256 + t; i < n4; i += 2048u * 256u) {
            float4 v = x[i];
            m = fmaxf(m, fmaxf(fmaxf(fabsf(v.x), fabsf(v.y)), fmaxf(fabsf(v.z), fabsf(v.w))));
        }
    } else {
        const int b = blk - 2048;
        m = fmaxf(fabsf(hs[b*3*NH + t]), fabsf(hs[b*3*NH + t + 256]));
    }
    red[t] = m;
    __syncthreads();
    for (int s = 128; s > 0; s >>= 1) {
        if (t < s) red[t] = fmaxf(red[t], red[t + s]);
        __syncthreads();
    }
    if (t == 0) g_part[blk] = red[0];
}

__global__ void k_scale2() {
    __shared__ float red[512];
    const int t = threadIdx.x;
    float mx = 0.f;
    for (int i = t; i < 2048; i += 512) mx = fmaxf(mx, g_part[i]);
    red[t] = mx;
    __syncthreads();
    for (int s = 256; s > 0; s >>= 1) {
        if (t < s) red[t] = fmaxf(red[t], red[t + s]);
        __syncthreads();
    }
    mx = fmaxf(red[0], 1e-20f);
    __syncthreads();
    float mh = (t < 64) ? g_part[2048 + t] : 0.f;
    red[t] = mh;
    __syncthreads();
    for (int s = 256; s > 0; s >>= 1) {
        if (t < s) red[t] = fmaxf(red[t], red[t + s]);
        __syncthreads();
    }
    if (t == 0) {
        float mhf = fmaxf(fmaxf(red[0], 1.0f), 1e-20f);
        g_sc[0] = mx / 32512.0f;
        g_sc[1] = mhf / 32512.0f;
        g_sc[2] = 32512.0f / mx;
        g_sc[3] = 32512.0f / mhf;
    }
}

__global__ void __launch_bounds__(512) k_prep(
    const float* __restrict__ x, const float* __restrict__ hs,
    const float* __restrict__ Wzx, const float* __restrict__ Wzh,
    const float* __restrict__ Wrx, const float* __restrict__ Wrh,
    const float* __restrict__ Wgx, const float* __restrict__ Wgh,
    const float* __restrict__ Wout,
    int8_t* __restrict__ qhi, int8_t* __restrict__ qlo,
    int8_t* __restrict__ wqh, int8_t* __restrict__ wql, float* __restrict__ sbv,
    float* __restrict__ hz, float* __restrict__ hr, float* __restrict__ h0c)
{
    __shared__ float sm[512];
    const int blk = blockIdx.x, t = threadIdx.x;
    const size_t WS = (size_t)WSTRIDE;

    if (blk < 2048) {
        const float invX = g_sc[2];
        for (size_t i = (size_t)blk * 512 + t; i < PLANE; i += 2048u * 512u)
            quant16(x[i], invX, &qhi[i], &qlo[i]);
    } else if (blk < 2176) {
        const int rel = blk - 2048;
        const int b = rel >> 1, gate = rel & 1;
        float h0v = hs[b*3*NH + t];
        sm[t] = h0v;
        if (gate == 0) h0c[b*NH + t] = h0v;
        __syncthreads();
        const float* W = gate ? Wrh : Wzh;
        float acc = 0.f;
        #pragma unroll 8
        for (int k = 0; k < 512; k++) acc = fmaf(sm[k], W[k*512 + t], acc);
        (gate ? hr : hz)[b*NH + t] = acc;
    } else {
        const int rel = blk - 2176;
        const int j = rel >> 9, n = rel & 511;
        const float *W, *W2 = nullptr;
        if (j == 12) {
            W = Wout;
        } else {
            int l = j >> 2, s = j & 3;
            if (s == 0)      { W = Wzx + l*WS; W2 = l ? (Wzh + l*WS) : nullptr; }
            else if (s == 1) { W = Wrx + l*WS; W2 = l ? (Wrh + l*WS) : nullptr; }
            else if (s == 2) { W = Wgx + l*WS; }
            else             { W = Wgh + l*WS; }
        }
        float v = W[(size_t)t * 512 + n];
        if (W2) v += W2[(size_t)t * 512 + n];
        sm[t] = fabsf(v);
        __syncthreads();
        for (int s = 256; s > 0; s >>= 1) {
            if (t < s) sm[t] = fmaxf(sm[t], sm[t + s]);
            __syncthreads();
        }
        float mx = fmaxf(sm[0], 1e-20f);
        float invS = 32512.0f / mx;
        quant16(v, invS,
                wqh + (size_t)j*WS + (size_t)n*512 + t,
                wql + (size_t)j*WS + (size_t)n*512 + t);
        if (t == 0) sbv[j*512 + n] = mx / 32512.0f;
    }
}

__global__ void k_tail(const float* __restrict__ hs,
                       const int8_t* __restrict__ h0h, const int8_t* __restrict__ h0l,
                       const int8_t* __restrict__ h1h, const int8_t* __restrict__ h1l,
                       float* __restrict__ out_h) {
    int b = blockIdx.x, n = threadIdx.x;
    float sH = g_sc[1];
    size_t last = ((size_t)b*NS + (NS-1)) * (size_t)NN + n;
    out_h[b*3*NH + n]        = hs[b*3*NH + n];
    out_h[b*3*NH + 512 + n]  = sH * (256.0f * (float)h0h[last] + (float)h0l[last]);
    out_h[b*3*NH + 1024 + n] = sH * (256.0f * (float)h1h[last] + (float)h1l[last]);
}

// ---------------- persistent int8x2 MMA GEMM with fused GRU epilogue ----------------
struct GP {
    const int8_t *Ahi, *Alo, *Bhi, *Blo;
    const float *sA, *sBv;
    float* Cf;
    int8_t *Chi, *Clo;
    const float *bias, *hterm, *h0c;
    const int8_t *hvhi, *hvlo;
    const float *sHv, *inv;
    const float *zb, *agb;
};

template<int EPI>
__global__ void __launch_bounds__(256, 2) gemm_i8(const GP p) {
    extern __shared__ char smem_raw[];
    const uint32_t base = smem_u32(smem_raw);
    const int tid = threadIdx.x;
    const int lane = tid & 31;
    const int w = tid >> 5;
    const int wr = w >> 2;          // 0..1 (32 rows)
    const int wc = w & 3;           // 0..3 (32 cols)

    const int pid = blockIdx.x;
    const int nloc = (NTILES - pid + NPERS - 1) / NPERS;
    const int total = nloc * 8;

    const int a_row = wr*32 + ((lane>>3)&1)*8 + (lane&7);
    const uint32_t a_lm = a_row*ROWB + ((((uint32_t)(lane>>4))*16) ^ (((uint32_t)a_row<<3)&0x30));
    const int b_row = wc*32 + (lane>>4)*8 + (lane&7);
    const uint32_t b_lm = b_row*ROWB + (((((uint32_t)(lane>>3))&1)*16) ^ (((uint32_t)b_row<<3)&0x30));

    const int crow = tid >> 2;          // 0..63
    const int ccs  = (tid & 3) * 16;
    const uint32_t cdc = (uint32_t)ccs ^ (((uint32_t)crow<<3)&0x30);

    auto issue = [&](int cc) {
        const int t = pid + (cc >> 3) * NPERS;
        const int ibm = (t >> 2) * BM;
        const int ibn = (t & 3) * BN;
        const int kk = (cc & 7) * KCH + ccs;
        const uint32_t sb = base + (cc & (NSLOT-1)) * SLOT;
        const uint32_t so = crow * ROWB + cdc;
        const size_t ga = (size_t)(ibm + crow) * 512 + kk;
        cp_async16(sb + A_HI_OFF + so, p.Ahi + ga);
        cp_async16(sb + A_LO_OFF + so, p.Alo + ga);
        #pragma unroll
        for (int i = 0; i < 2; i++) {
            const int row = crow + i * 64;
            const size_t gb = (size_t)(ibn + row) * 512 + kk;
            const uint32_t sob = row * ROWB + cdc;
            cp_async16(sb + B_HI_OFF + sob, p.Bhi + gb);
            cp_async16(sb + B_LO_OFF + sob, p.Blo + gb);
        }
    };

    issue(0); cp_commit();
    issue(1); cp_commit();
    issue(2); cp_commit();

    const float sA = p.sA[0];
    int cc = 0;
    for (int ti = 0; ti < nloc; ti++) {
        const int t = pid + ti * NPERS;
        const int bm = (t >> 2) * BM;
        const int bn = (t & 3) * BN;

        int c0[2][4][4], c1[2][4][4];
        #pragma unroll
        for (int i = 0; i < 2; i++)
            #pragma unroll
            for (int j = 0; j < 4; j++)
                #pragma unroll
                for (int e = 0; e < 4; e++) { c0[i][j][e] = 0; c1[i][j][e] = 0; }

        for (int s = 0; s < 8; s++, cc++) {
            const int ahead = total - 1 - cc;
            if (ahead >= 2) cp_wait<2>(); else if (ahead == 1) cp_wait<1>(); else cp_wait<0>();
            __syncthreads();
            if (cc + 3 < total) { issue(cc + 3); cp_commit(); }

            const uint32_t sb = base + (cc & (NSLOT-1)) * SLOT;
            #pragma unroll
            for (int ks = 0; ks < 2; ks++) {
                const uint32_t kx = (uint32_t)ks << 5;
                uint32_t ah[2][4], bh[4][2];
                #pragma unroll
                for (int mt = 0; mt < 2; mt++)
                    ldmatrix4(ah[mt][0], ah[mt][1], ah[mt][2], ah[mt][3],
                              (sb + A_HI_OFF + a_lm + mt * (16*ROWB)) ^ kx);
                #pragma unroll
                for (int np = 0; np < 2; np++) {
                    uint32_t r0, r1, r2, r3;
                    ldmatrix4(r0, r1, r2, r3, (sb + B_HI_OFF + b_lm + np * (16*ROWB)) ^ kx);
                    bh[np*2][0] = r0;   bh[np*2][1] = r1;
                    bh[np*2+1][0] = r2; bh[np*2+1][1] = r3;
                }
                #pragma unroll
                for (int mt = 0; mt < 2; mt++)
                    #pragma unroll
                    for (int nt = 0; nt < 4; nt++)
                        mma_s8(c0[mt][nt], ah[mt], bh[nt]);
                {   // hl
                    uint32_t bl[4][2];
                    #pragma unroll
                    for (int np = 0; np < 2; np++) {
                        uint32_t r0, r1, r2, r3;
                        ldmatrix4(r0, r1, r2, r3, (sb + B_LO_OFF + b_lm + np * (16*ROWB)) ^ kx);
                        bl[np*2][0] = r0;   bl[np*2][1] = r1;
                        bl[np*2+1][0] = r2; bl[np*2+1][1] = r3;
                    }
                    #pragma unroll
                    for (int mt = 0; mt < 2; mt++)
                        #pragma unroll
                        for (int nt = 0; nt < 4; nt++)
                            mma_s8(c1[mt][nt], ah[mt], bl[nt]);
                }
                {   // lh
                    uint32_t al[2][4];
                    #pragma unroll
                    for (int mt = 0; mt < 2; mt++)
                        ldmatrix4(al[mt][0], al[mt][1], al[mt][2], al[mt][3],
                                  (sb + A_LO_OFF + a_lm + mt * (16*ROWB)) ^ kx);
                    #pragma unroll
                    for (int mt = 0; mt < 2; mt++)
                        #pragma unroll
                        for (int nt = 0; nt < 4; nt++)
                            mma_s8(c1[mt][nt], al[mt], bh[nt]);
                }
            }
        }

        // ---- fused epilogue (overlaps with next tile's in-flight loads) ----
        const int rbase = bm + wr * 32;
        const int cbase = bn + wc * 32;
        #pragma unroll
        for (int mt = 0; mt < 2; mt++) {
            #pragma unroll
            for (int er = 0; er < 2; er++) {
                const int gm = rbase + mt*16 + (lane >> 2) + er*8;
                const int bb = gm >> 10;
                #pragma unroll
                for (int nt = 0; nt < 4; nt++) {
                    #pragma unroll
                    for (int ec = 0; ec < 2; ec++) {
                        const int gn = cbase + nt*8 + (lane & 3)*2 + ec;
                        const size_t idx = (size_t)gm * NN + gn;
                        const int e = er*2 + ec;
                        float val = sA * p.sBv[gn] *
                            (65536.0f * (float)c0[mt][nt][e] + 256.0f * (float)c1[mt][nt][e]);
                        if (EPI == 1) {
                            val += p.bias[gn];
                            if (p.hterm) val += p.hterm[bb * NH + gn];
                            p.Cf[idx] = 1.f / (1.f + __expf(-val));
                        } else if (EPI == 2) {
                            val += p.bias[gn];
                            if (p.hterm) val += p.hterm[bb * NH + gn];
                            float r_ = 1.f / (1.f + __expf(-val));
                            float hv = p.h0c ? p.h0c[bb * NH + gn]
                                : p.sHv[0] * (256.0f * (float)p.hvhi[idx] + (float)p.hvlo[idx]);
                            quant16(r_ * hv, p.inv[0], &p.Chi[idx], &p.Clo[idx]);
                        } else if (EPI == 3) {
                            p.Cf[idx] = val + p.bias[gn];
                        } else {
                            float g = tanhf(val + p.agb[idx]);
                            float z = p.zb[idx];
                            float hv = p.h0c ? p.h0c[bb * NH + gn]
                                : p.sHv[0] * (256.0f * (float)p.hvhi[idx] + (float)p.hvlo[idx]);
                            quant16(z * hv + (1.f - z) * g, p.inv[0], &p.Chi[idx], &p.Clo[idx]);
                        }
                    }
                }
            }
        }
    }
}

// ---------------- host ----------------
extern "C" void kernel_launch(void* const* d_in, const int* in_sizes, int n_in,
                              void* d_out, int out_size) {
    const float* input = (const float*)d_in[0];
    const float* hs    = (const float*)d_in[1];
    const float* Wzx   = (const float*)d_in[2];
    const float* bzx   = (const float*)d_in[3];
    const float* Wzh   = (const float*)d_in[4];
    const float* Wrx   = (const float*)d_in[5];
    const float* brx   = (const float*)d_in[6];
    const float* Wrh   = (const float*)d_in[7];
    const float* Wgx   = (const float*)d_in[8];
    const float* bgx   = (const float*)d_in[9];
    const float* Wgh   = (const float*)d_in[10];
    const float* Wout  = (const float*)d_in[11];
    const float* bout  = (const float*)d_in[12];
    float* out = (float*)d_out;

    int8_t *qhi, *qlo, *wqh, *wql;
    float *sbv, *z, *ag, *hz, *hr, *h0c, *sc;
    cudaGetSymbolAddress((void**)&qhi, g_qhi);
    cudaGetSymbolAddress((void**)&qlo, g_qlo);
    cudaGetSymbolAddress((void**)&wqh, g_wqh);
    cudaGetSymbolAddress((void**)&wql, g_wql);
    cudaGetSymbolAddress((void**)&sbv, g_sbv);
    cudaGetSymbolAddress((void**)&z,   g_z);
    cudaGetSymbolAddress((void**)&ag,  g_ag);
    cudaGetSymbolAddress((void**)&hz,  g_hz);
    cudaGetSymbolAddress((void**)&hr,  g_hr);
    cudaGetSymbolAddress((void**)&h0c, g_h0c);
    cudaGetSymbolAddress((void**)&sc,  g_sc);

    cudaFuncSetAttribute(gemm_i8<1>, cudaFuncAttributeMaxDynamicSharedMemorySize, SMEM_BYTES);
    cudaFuncSetAttribute(gemm_i8<2>, cudaFuncAttributeMaxDynamicSharedMemorySize, SMEM_BYTES);
    cudaFuncSetAttribute(gemm_i8<3>, cudaFuncAttributeMaxDynamicSharedMemorySize, SMEM_BYTES);
    cudaFuncSetAttribute(gemm_i8<4>, cudaFuncAttributeMaxDynamicSharedMemorySize, SMEM_BYTES);

    // ---- prep ----
    k_stat<<<2112, 256>>>((const float4*)input, hs);
    k_scale2<<<1, 512>>>();
    k_prep<<<8832, 512>>>(input, hs, Wzx, Wzh, Wrx, Wrh, Wgx, Wgh, Wout,
                          qhi, qlo, wqh, wql, sbv, hz, hr, h0c);

    const dim3 grid(NPERS);
    const dim3 blk(256);
    int8_t* QH[5]; int8_t* QL[5];
    for (int i = 0; i < 5; i++) { QH[i] = qhi + (size_t)i*PLANE; QL[i] = qlo + (size_t)i*PLANE; }
    const float *sX = sc + 0, *sH = sc + 1, *invH = sc + 3;

    auto run = [&](int epi, int aplane, const float* sa, int wslot,
                   float* cf, int cplane,
                   const float* bias, const float* hterm, const float* h0cp,
                   int hvplane, const float* zb, const float* agb) {
        GP p{};
        p.Ahi = QH[aplane]; p.Alo = QL[aplane];
        p.Bhi = wqh + (size_t)wslot*WSTRIDE; p.Blo = wql + (size_t)wslot*WSTRIDE;
        p.sA = sa; p.sBv = sbv + wslot*512;
        p.Cf = cf;
        p.Chi = cplane >= 0 ? QH[cplane] : nullptr;
        p.Clo = cplane >= 0 ? QL[cplane] : nullptr;
        p.bias = bias; p.hterm = hterm; p.h0c = h0cp;
        p.hvhi = hvplane >= 0 ? QH[hvplane] : nullptr;
        p.hvlo = hvplane >= 0 ? QL[hvplane] : nullptr;
        p.sHv = sH; p.inv = invH;
        p.zb = zb; p.agb = agb;
        if (epi == 1)      gemm_i8<1><<<grid, blk, SMEM_BYTES>>>(p);
        else if (epi == 2) gemm_i8<2><<<grid, blk, SMEM_BYTES>>>(p);
        else if (epi == 3) gemm_i8<3><<<grid, blk, SMEM_BYTES>>>(p);
        else               gemm_i8<4><<<grid, blk, SMEM_BYTES>>>(p);
    };

    // ---- layer 0 (h = const h0; x = plane 0) ----
    run(1, 0, sX, 0,  z,  -1, bzx,      hz,      nullptr, -1, nullptr, nullptr);
    run(2, 0, sX, 1,  nullptr, 1, brx,  hr,      h0c,     -1, nullptr, nullptr);
    run(3, 0, sX, 2,  ag, -1, bgx,      nullptr, nullptr, -1, nullptr, nullptr);
    run(4, 1, sH, 3,  nullptr, 2, nullptr, nullptr, h0c,  -1, z, ag);
    // ---- layer 1 (x == h == plane 2) ----
    run(1, 2, sH, 4,  z,  -1, bzx+512,  nullptr, nullptr, -1, nullptr, nullptr);
    run(2, 2, sH, 5,  nullptr, 1, brx+512, nullptr, nullptr, 2, nullptr, nullptr);
    run(3, 2, sH, 6,  ag, -1, bgx+512,  nullptr, nullptr, -1, nullptr, nullptr);
    run(4, 1, sH, 7,  nullptr, 3, nullptr, nullptr, nullptr, 2, z, ag);
    // ---- layer 2 (x == h == plane 3) ----
    run(1, 3, sH, 8,  z,  -1, bzx+1024, nullptr, nullptr, -1, nullptr, nullptr);
    run(2, 3, sH, 9,  nullptr, 1, brx+1024, nullptr, nullptr, 3, nullptr, nullptr);
    run(3, 3, sH, 10, ag, -1, bgx+1024, nullptr, nullptr, -1, nullptr, nullptr);
    run(4, 1, sH, 11, nullptr, 4, nullptr, nullptr, nullptr, 3, z, ag);
    // ---- output projection ----
    run(3, 4, sH, 12, out, -1, bout,    nullptr, nullptr, -1, nullptr, nullptr);

    k_tail<<<64, 512>>>(hs, QH[2], QL[2], QH[3], QL[3], out + PLANE);
}

// round 15
// speedup vs baseline: 1.0371x; 1.0371x over previous
#include <cuda_runtime.h>
#include <cstdint>

// ---------------- problem constants ----------------
#define NB 64
#define NS 1024
#define NH 512
#define NM (NB*NS)
#define NN 512
#define WSTRIDE (512*512)
#define PLANE ((size_t)NM*NN)

// GEMM tiling: CTA 64x128, 8 warps (2x4), warp tile 32x32, K-chunk 64 (int8).
#define BM 64
#define BN 128
#define KCH 64
#define NSUP 8
#define ROWB 64
#define A_TILE_B (64*ROWB)      // 4096
#define B_TILE_B (128*ROWB)     // 8192
#define SLOT (2*A_TILE_B + 2*B_TILE_B)  // 24576
#define NSLOT 4
#define SMEM_BYTES (NSLOT*SLOT) // 98304 -> 2 CTAs/SM

#define A_HI_OFF 0
#define A_LO_OFF A_TILE_B
#define B_HI_OFF (2*A_TILE_B)
#define B_LO_OFF (2*A_TILE_B + B_TILE_B)

// ---------------- device scratch ----------------
__device__ int8_t g_qhi[(size_t)5*PLANE];   // act planes: 0=X 1=rh 2=h0 3=h1 4=h2
__device__ int8_t g_qlo[(size_t)5*PLANE];
__device__ int8_t g_wqh[(size_t)13*WSTRIDE];
__device__ int8_t g_wql[(size_t)13*WSTRIDE];
__device__ float  g_sbv[13*512];
__device__ float  g_z [PLANE];
__device__ float  g_ag[PLANE];
__device__ float  g_hz [NB*NH];
__device__ float  g_hr [NB*NH];
__device__ float  g_h0c[NB*NH];
__device__ float  g_part[2112];
__device__ float  g_sc[4];                   // sX, sH, invX, invH

// ---------------- helpers ----------------
__device__ __forceinline__ uint32_t smem_u32(const void* p) {
    uint32_t a;
    asm("{ .reg .u64 t; cvta.to.shared.u64 t, %1; cvt.u32.u64 %0, t; }" : "=r"(a) : "l"(p));
    return a;
}
__device__ __forceinline__ void cp_async16(uint32_t dst, const void* src) {
    asm volatile("cp.async.cg.shared.global [%0], [%1], 16;" :: "r"(dst), "l"(src) : "memory");
}
__device__ __forceinline__ void cp_commit() { asm volatile("cp.async.commit_group;" ::: "memory"); }
template<int N>
__device__ __forceinline__ void cp_wait() { asm volatile("cp.async.wait_group %0;" :: "n"(N) : "memory"); }
__device__ __forceinline__ void ldmatrix4(uint32_t& r0, uint32_t& r1, uint32_t& r2, uint32_t& r3, uint32_t addr) {
    asm volatile("ldmatrix.sync.aligned.m8n8.x4.shared.b16 {%0,%1,%2,%3}, [%4];"
                 : "=r"(r0), "=r"(r1), "=r"(r2), "=r"(r3) : "r"(addr));
}
__device__ __forceinline__ void mma_s8(int* d, const uint32_t* a, const uint32_t* b) {
    asm volatile("mma.sync.aligned.m16n8k32.row.col.s32.s8.s8.s32 "
        "{%0,%1,%2,%3}, {%4,%5,%6,%7}, {%8,%9}, {%0,%1,%2,%3};"
        : "+r"(d[0]), "+r"(d[1]), "+r"(d[2]), "+r"(d[3])
        : "r"(a[0]), "r"(a[1]), "r"(a[2]), "r"(a[3]), "r"(b[0]), "r"(b[1]));
}
__device__ __forceinline__ void quant16(float v, float invS, int8_t* hp, int8_t* lp) {
    int q = __float2int_rn(v * invS);
    q = max(-32512, min(32512, q));
    int h = (q + 128) >> 8;
    *hp = (int8_t)h;
    *lp = (int8_t)(q - (h << 8));
}

// ---------------- prep (3 launches) ----------------
__global__ void k_stat(const float4* __restrict__ x, const float* __restrict__ hs) {
    __shared__ float red[256];
    const int blk = blockIdx.x, t = threadIdx.x;
    float m = 0.f;
    if (blk < 2048) {
        const size_t n4 = PLANE / 4;
        for (size_t i = (size_t)blk * 256 + t; i < n4; i += 2048u * 256u) {
            float4 v = x[i];
            m = fmaxf(m, fmaxf(fmaxf(fabsf(v.x), fabsf(v.y)), fmaxf(fabsf(v.z), fabsf(v.w))));
        }
    } else {
        const int b = blk - 2048;
        m = fmaxf(fabsf(hs[b*3*NH + t]), fabsf(hs[b*3*NH + t + 256]));
    }
    red[t] = m;
    __syncthreads();
    for (int s = 128; s > 0; s >>= 1) {
        if (t < s) red[t] = fmaxf(red[t], red[t + s]);
        __syncthreads();
    }
    if (t == 0) g_part[blk] = red[0];
}

__global__ void k_scale2() {
    __shared__ float red[512];
    const int t = threadIdx.x;
    float mx = 0.f;
    for (int i = t; i < 2048; i += 512) mx = fmaxf(mx, g_part[i]);
    red[t] = mx;
    __syncthreads();
    for (int s = 256; s > 0; s >>= 1) {
        if (t < s) red[t] = fmaxf(red[t], red[t + s]);
        __syncthreads();
    }
    mx = fmaxf(red[0], 1e-20f);
    __syncthreads();
    float mh = (t < 64) ? g_part[2048 + t] : 0.f;
    red[t] = mh;
    __syncthreads();
    for (int s = 256; s > 0; s >>= 1) {
        if (t < s) red[t] = fmaxf(red[t], red[t + s]);
        __syncthreads();
    }
    if (t == 0) {
        float mhf = fmaxf(fmaxf(red[0], 1.0f), 1e-20f);
        g_sc[0] = mx / 32512.0f;
        g_sc[1] = mhf / 32512.0f;
        g_sc[2] = 32512.0f / mx;
        g_sc[3] = 32512.0f / mhf;
    }
}

__global__ void __launch_bounds__(512) k_prep(
    const float* __restrict__ x, const float* __restrict__ hs,
    const float* __restrict__ Wzx, const float* __restrict__ Wzh,
    const float* __restrict__ Wrx, const float* __restrict__ Wrh,
    const float* __restrict__ Wgx, const float* __restrict__ Wgh,
    const float* __restrict__ Wout,
    int8_t* __restrict__ qhi, int8_t* __restrict__ qlo,
    int8_t* __restrict__ wqh, int8_t* __restrict__ wql, float* __restrict__ sbv,
    float* __restrict__ hz, float* __restrict__ hr, float* __restrict__ h0c)
{
    __shared__ float sm[512];
    const int blk = blockIdx.x, t = threadIdx.x;
    const size_t WS = (size_t)WSTRIDE;

    if (blk < 2048) {
        const float invX = g_sc[2];
        for (size_t i = (size_t)blk * 512 + t; i < PLANE; i += 2048u * 512u)
            quant16(x[i], invX, &qhi[i], &qlo[i]);
    } else if (blk < 2176) {
        const int rel = blk - 2048;
        const int b = rel >> 1, gate = rel & 1;
        float h0v = hs[b*3*NH + t];
        sm[t] = h0v;
        if (gate == 0) h0c[b*NH + t] = h0v;
        __syncthreads();
        const float* W = gate ? Wrh : Wzh;
        float acc = 0.f;
        #pragma unroll 8
        for (int k = 0; k < 512; k++) acc = fmaf(sm[k], W[k*512 + t], acc);
        (gate ? hr : hz)[b*NH + t] = acc;
    } else {
        const int rel = blk - 2176;
        const int j = rel >> 9, n = rel & 511;
        const float *W, *W2 = nullptr;
        if (j == 12) {
            W = Wout;
        } else {
            int l = j >> 2, s = j & 3;
            if (s == 0)      { W = Wzx + l*WS; W2 = l ? (Wzh + l*WS) : nullptr; }
            else if (s == 1) { W = Wrx + l*WS; W2 = l ? (Wrh + l*WS) : nullptr; }
            else if (s == 2) { W = Wgx + l*WS; }
            else             { W = Wgh + l*WS; }
        }
        float v = W[(size_t)t * 512 + n];
        if (W2) v += W2[(size_t)t * 512 + n];
        sm[t] = fabsf(v);
        __syncthreads();
        for (int s = 256; s > 0; s >>= 1) {
            if (t < s) sm[t] = fmaxf(sm[t], sm[t + s]);
            __syncthreads();
        }
        float mx = fmaxf(sm[0], 1e-20f);
        float invS = 32512.0f / mx;
        quant16(v, invS,
                wqh + (size_t)j*WS + (size_t)n*512 + t,
                wql + (size_t)j*WS + (size_t)n*512 + t);
        if (t == 0) sbv[j*512 + n] = mx / 32512.0f;
    }
}

__global__ void k_tail(const float* __restrict__ hs,
                       const int8_t* __restrict__ h0h, const int8_t* __restrict__ h0l,
                       const int8_t* __restrict__ h1h, const int8_t* __restrict__ h1l,
                       float* __restrict__ out_h) {
    int b = blockIdx.x, n = threadIdx.x;
    float sH = g_sc[1];
    size_t last = ((size_t)b*NS + (NS-1)) * (size_t)NN + n;
    out_h[b*3*NH + n]        = hs[b*3*NH + n];
    out_h[b*3*NH + 512 + n]  = sH * (256.0f * (float)h0h[last] + (float)h0l[last]);
    out_h[b*3*NH + 1024 + n] = sH * (256.0f * (float)h1h[last] + (float)h1l[last]);
}

// ---------------- int8x2 MMA GEMM with fused GRU epilogue ----------------
// C = sA*sB[n]*(65536*acc_hh + 256*acc_mid), acc exact int32.
struct GP {
    const int8_t *Ahi, *Alo, *Bhi, *Blo;
    const float *sA, *sBv;
    float* Cf;
    int8_t *Chi, *Clo;
    const float *bias, *hterm, *h0c;
    const int8_t *hvhi, *hvlo;
    const float *sHv, *inv;
    const float *zb, *agb;
};

template<int EPI>
__global__ void __launch_bounds__(256, 2) gemm_i8(const GP p) {
    extern __shared__ char smem_raw[];
    const uint32_t base = smem_u32(smem_raw);
    const int tid = threadIdx.x;
    const int lane = tid & 31;
    const int w = tid >> 5;
    const int wr = w >> 2;          // 0..1 (32 rows each)
    const int wc = w & 3;           // 0..3 (32 cols each)
    const int bm = blockIdx.y * BM;
    const int bn = blockIdx.x * BN;

    int c0[2][4][4], c1[2][4][4];
    #pragma unroll
    for (int i = 0; i < 2; i++)
        #pragma unroll
        for (int j = 0; j < 4; j++)
            #pragma unroll
            for (int e = 0; e < 4; e++) { c0[i][j][e] = 0; c1[i][j][e] = 0; }

    const int a_row = wr*32 + ((lane>>3)&1)*8 + (lane&7);
    const uint32_t a_lm = a_row*ROWB + ((((uint32_t)(lane>>4))*16) ^ (((uint32_t)a_row<<3)&0x30));
    const int b_row = wc*32 + (lane>>4)*8 + (lane&7);
    const uint32_t b_lm = b_row*ROWB + (((((uint32_t)(lane>>3))&1)*16) ^ (((uint32_t)b_row<<3)&0x30));

    // copy: A tiles 64x4 chunks (1/thr each), B tiles 128x4 (2/thr each) -> 6 cp/thr
    const int crow = tid >> 2;          // 0..63
    const int ccs  = (tid & 3) * 16;
    const uint32_t cdc = (uint32_t)ccs ^ (((uint32_t)crow<<3)&0x30);
    auto issue = [&](int s) {
        const int kk = s * KCH + ccs;
        const uint32_t sb = base + (s & (NSLOT-1)) * SLOT;
        const uint32_t so = crow * ROWB + cdc;
        const size_t ga = (size_t)(bm + crow) * 512 + kk;
        cp_async16(sb + A_HI_OFF + so, p.Ahi + ga);
        cp_async16(sb + A_LO_OFF + so, p.Alo + ga);
        #pragma unroll
        for (int i = 0; i < 2; i++) {
            const int row = crow + i * 64;
            const size_t gb = (size_t)(bn + row) * 512 + kk;
            const uint32_t sob = row * ROWB + cdc;
            cp_async16(sb + B_HI_OFF + sob, p.Bhi + gb);
            cp_async16(sb + B_LO_OFF + sob, p.Blo + gb);
        }
    };

    issue(0); cp_commit();
    issue(1); cp_commit();
    issue(2); cp_commit();

    for (int s = 0; s < NSUP; s++) {
        if (s < NSUP-2) cp_wait<2>(); else if (s == NSUP-2) cp_wait<1>(); else cp_wait<0>();
        __syncthreads();
        if (s + 3 < NSUP) { issue(s + 3); cp_commit(); }

        const uint32_t sb = base + (s & (NSLOT-1)) * SLOT;
        #pragma unroll
        for (int ks = 0; ks < 2; ks++) {
            const uint32_t kx = (uint32_t)ks << 5;
            // ---- hoisted fragment loads: all 8 ldmatrix4 back-to-back ----
            uint32_t ah[2][4], al[2][4], bh[4][2], bl[4][2];
            #pragma unroll
            for (int mt = 0; mt < 2; mt++)
                ldmatrix4(ah[mt][0], ah[mt][1], ah[mt][2], ah[mt][3],
                          (sb + A_HI_OFF + a_lm + mt * (16*ROWB)) ^ kx);
            #pragma unroll
            for (int np = 0; np < 2; np++) {
                uint32_t r0, r1, r2, r3;
                ldmatrix4(r0, r1, r2, r3, (sb + B_HI_OFF + b_lm + np * (16*ROWB)) ^ kx);
                bh[np*2][0] = r0;   bh[np*2][1] = r1;
                bh[np*2+1][0] = r2; bh[np*2+1][1] = r3;
            }
            #pragma unroll
            for (int np = 0; np < 2; np++) {
                uint32_t r0, r1, r2, r3;
                ldmatrix4(r0, r1, r2, r3, (sb + B_LO_OFF + b_lm + np * (16*ROWB)) ^ kx);
                bl[np*2][0] = r0;   bl[np*2][1] = r1;
                bl[np*2+1][0] = r2; bl[np*2+1][1] = r3;
            }
            #pragma unroll
            for (int mt = 0; mt < 2; mt++)
                ldmatrix4(al[mt][0], al[mt][1], al[mt][2], al[mt][3],
                          (sb + A_LO_OFF + a_lm + mt * (16*ROWB)) ^ kx);
            // ---- dense mma burst: 24 mmas, hh -> hl -> lh ----
            #pragma unroll
            for (int mt = 0; mt < 2; mt++)
                #pragma unroll
                for (int nt = 0; nt < 4; nt++)
                    mma_s8(c0[mt][nt], ah[mt], bh[nt]);
            #pragma unroll
            for (int mt = 0; mt < 2; mt++)
                #pragma unroll
                for (int nt = 0; nt < 4; nt++)
                    mma_s8(c1[mt][nt], ah[mt], bl[nt]);
            #pragma unroll
            for (int mt = 0; mt < 2; mt++)
                #pragma unroll
                for (int nt = 0; nt < 4; nt++)
                    mma_s8(c1[mt][nt], al[mt], bh[nt]);
        }
    }

    // ---- fused epilogue ----
    const int rbase = bm + wr * 32;
    const int cbase = bn + wc * 32;
    const float sA = p.sA[0];
    #pragma unroll
    for (int mt = 0; mt < 2; mt++) {
        #pragma unroll
        for (int er = 0; er < 2; er++) {
            const int gm = rbase + mt*16 + (lane >> 2) + er*8;
            const int bb = gm >> 10;
            #pragma unroll
            for (int nt = 0; nt < 4; nt++) {
                #pragma unroll
                for (int ec = 0; ec < 2; ec++) {
                    const int gn = cbase + nt*8 + (lane & 3)*2 + ec;
                    const size_t idx = (size_t)gm * NN + gn;
                    const int e = er*2 + ec;
                    float val = sA * p.sBv[gn] *
                        (65536.0f * (float)c0[mt][nt][e] + 256.0f * (float)c1[mt][nt][e]);
                    if (EPI == 1) {
                        val += p.bias[gn];
                        if (p.hterm) val += p.hterm[bb * NH + gn];
                        p.Cf[idx] = 1.f / (1.f + __expf(-val));
                    } else if (EPI == 2) {
                        val += p.bias[gn];
                        if (p.hterm) val += p.hterm[bb * NH + gn];
                        float r_ = 1.f / (1.f + __expf(-val));
                        float hv = p.h0c ? p.h0c[bb * NH + gn]
                            : p.sHv[0] * (256.0f * (float)p.hvhi[idx] + (float)p.hvlo[idx]);
                        quant16(r_ * hv, p.inv[0], &p.Chi[idx], &p.Clo[idx]);
                    } else if (EPI == 3) {
                        p.Cf[idx] = val + p.bias[gn];
                    } else {
                        float g = tanhf(val + p.agb[idx]);
                        float z = p.zb[idx];
                        float hv = p.h0c ? p.h0c[bb * NH + gn]
                            : p.sHv[0] * (256.0f * (float)p.hvhi[idx] + (float)p.hvlo[idx]);
                        quant16(z * hv + (1.f - z) * g, p.inv[0], &p.Chi[idx], &p.Clo[idx]);
                    }
                }
            }
        }
    }
}

// ---------------- host ----------------
extern "C" void kernel_launch(void* const* d_in, const int* in_sizes, int n_in,
                              void* d_out, int out_size) {
    const float* input = (const float*)d_in[0];
    const float* hs    = (const float*)d_in[1];
    const float* Wzx   = (const float*)d_in[2];
    const float* bzx   = (const float*)d_in[3];
    const float* Wzh   = (const float*)d_in[4];
    const float* Wrx   = (const float*)d_in[5];
    const float* brx   = (const float*)d_in[6];
    const float* Wrh   = (const float*)d_in[7];
    const float* Wgx   = (const float*)d_in[8];
    const float* bgx   = (const float*)d_in[9];
    const float* Wgh   = (const float*)d_in[10];
    const float* Wout  = (const float*)d_in[11];
    const float* bout  = (const float*)d_in[12];
    float* out = (float*)d_out;

    int8_t *qhi, *qlo, *wqh, *wql;
    float *sbv, *z, *ag, *hz, *hr, *h0c, *sc;
    cudaGetSymbolAddress((void**)&qhi, g_qhi);
    cudaGetSymbolAddress((void**)&qlo, g_qlo);
    cudaGetSymbolAddress((void**)&wqh, g_wqh);
    cudaGetSymbolAddress((void**)&wql, g_wql);
    cudaGetSymbolAddress((void**)&sbv, g_sbv);
    cudaGetSymbolAddress((void**)&z,   g_z);
    cudaGetSymbolAddress((void**)&ag,  g_ag);
    cudaGetSymbolAddress((void**)&hz,  g_hz);
    cudaGetSymbolAddress((void**)&hr,  g_hr);
    cudaGetSymbolAddress((void**)&h0c, g_h0c);
    cudaGetSymbolAddress((void**)&sc,  g_sc);

    cudaFuncSetAttribute(gemm_i8<1>, cudaFuncAttributeMaxDynamicSharedMemorySize, SMEM_BYTES);
    cudaFuncSetAttribute(gemm_i8<2>, cudaFuncAttributeMaxDynamicSharedMemorySize, SMEM_BYTES);
    cudaFuncSetAttribute(gemm_i8<3>, cudaFuncAttributeMaxDynamicSharedMemorySize, SMEM_BYTES);
    cudaFuncSetAttribute(gemm_i8<4>, cudaFuncAttributeMaxDynamicSharedMemorySize, SMEM_BYTES);

    // ---- prep ----
    k_stat<<<2112, 256>>>((const float4*)input, hs);
    k_scale2<<<1, 512>>>();
    k_prep<<<8832, 512>>>(input, hs, Wzx, Wzh, Wrx, Wrh, Wgx, Wgh, Wout,
                          qhi, qlo, wqh, wql, sbv, hz, hr, h0c);

    const dim3 grid(NN / BN, NM / BM);   // (4, 1024)
    const dim3 blk(256);
    int8_t* QH[5]; int8_t* QL[5];
    for (int i = 0; i < 5; i++) { QH[i] = qhi + (size_t)i*PLANE; QL[i] = qlo + (size_t)i*PLANE; }
    const float *sX = sc + 0, *sH = sc + 1, *invH = sc + 3;

    auto run = [&](int epi, int aplane, const float* sa, int wslot,
                   float* cf, int cplane,
                   const float* bias, const float* hterm, const float* h0cp,
                   int hvplane, const float* zb, const float* agb) {
        GP p{};
        p.Ahi = QH[aplane]; p.Alo = QL[aplane];
        p.Bhi = wqh + (size_t)wslot*WSTRIDE; p.Blo = wql + (size_t)wslot*WSTRIDE;
        p.sA = sa; p.sBv = sbv + wslot*512;
        p.Cf = cf;
        p.Chi = cplane >= 0 ? QH[cplane] : nullptr;
        p.Clo = cplane >= 0 ? QL[cplane] : nullptr;
        p.bias = bias; p.hterm = hterm; p.h0c = h0cp;
        p.hvhi = hvplane >= 0 ? QH[hvplane] : nullptr;
        p.hvlo = hvplane >= 0 ? QL[hvplane] : nullptr;
        p.sHv = sH; p.inv = invH;
        p.zb = zb; p.agb = agb;
        if (epi == 1)      gemm_i8<1><<<grid, blk, SMEM_BYTES>>>(p);
        else if (epi == 2) gemm_i8<2><<<grid, blk, SMEM_BYTES>>>(p);
        else if (epi == 3) gemm_i8<3><<<grid, blk, SMEM_BYTES>>>(p);
        else               gemm_i8<4><<<grid, blk, SMEM_BYTES>>>(p);
    };

    // ---- layer 0 (h = const h0; x = plane 0) ----
    run(1, 0, sX, 0,  z,  -1, bzx,      hz,      nullptr, -1, nullptr, nullptr);
    run(2, 0, sX, 1,  nullptr, 1, brx,  hr,      h0c,     -1, nullptr, nullptr);
    run(3, 0, sX, 2,  ag, -1, bgx,      nullptr, nullptr, -1, nullptr, nullptr);
    run(4, 1, sH, 3,  nullptr, 2, nullptr, nullptr, h0c,  -1, z, ag);
    // ---- layer 1 (x == h == plane 2) ----
    run(1, 2, sH, 4,  z,  -1, bzx+512,  nullptr, nullptr, -1, nullptr, nullptr);
    run(2, 2, sH, 5,  nullptr, 1, brx+512, nullptr, nullptr, 2, nullptr, nullptr);
    run(3, 2, sH, 6,  ag, -1, bgx+512,  nullptr, nullptr, -1, nullptr, nullptr);
    run(4, 1, sH, 7,  nullptr, 3, nullptr, nullptr, nullptr, 2, z, ag);
    // ---- layer 2 (x == h == plane 3) ----
    run(1, 3, sH, 8,  z,  -1, bzx+1024, nullptr, nullptr, -1, nullptr, nullptr);
    run(2, 3, sH, 9,  nullptr, 1, brx+1024, nullptr, nullptr, 3, nullptr, nullptr);
    run(3, 3, sH, 10, ag, -1, bgx+1024, nullptr, nullptr, -1, nullptr, nullptr);
    run(4, 1, sH, 11, nullptr, 4, nullptr, nullptr, nullptr, 3, z, ag);
    // ---- output projection ----
    run(3, 4, sH, 12, out, -1, bout,    nullptr, nullptr, -1, nullptr, nullptr);

    k_tail<<<64, 512>>>(hs, QH[2], QL[2], QH[3], QL[3], out + PLANE);
}